// round 16
// baseline (speedup 1.0000x reference)
#include <cuda_runtime.h>
#include <cuda_fp16.h>
#include <mma.h>
#include <math.h>
#include <cstdint>

using namespace nvcuda;

// Problem dims (fixed by the reference)
#define BB 4
#define TT 2048
#define CC 1024
#define HH 4096
#define MROWS (BB * TT)          // 8192

// ---------------- scratch (device globals; no allocation allowed) ----------
__device__ __half s_h   [MROWS * CC];          // ln1 out (fp16)
__device__ __half s_qkv [MROWS * 3 * CC];      // qkv (fp16)
__device__ __half s_att [(long)BB * TT * TT];  // attention logits/probs (fp16)
__device__ __half s_y   [MROWS * CC];          // att @ v (fp16)
__device__ __half s_h2  [MROWS * CC];          // ln2 out (fp16)
__device__ __half s_fc  [MROWS * HH];          // gelu(fc) (fp16)
// fp16 weight copies (one contiguous region, converted by a single kernel)
#define WA_OFF 0L
#define WP_OFF ((long)CC * 3 * CC)
#define WF_OFF (WP_OFF + (long)CC * CC)
#define WM_OFF (WF_OFF + (long)CC * HH)
#define W_TOTAL (WM_OFF + (long)HH * CC)
__device__ __half s_w16[W_TOTAL];

// ---------------- helpers ---------------------------------------------------
__device__ __forceinline__ float gelu_f(float x) {
    const float c = 0.7978845608028654f;
    float x3 = x * x * x;
    return 0.5f * x * (1.0f + tanhf(c * (x + 0.044715f * x3)));
}

__device__ __forceinline__ void cp_async16(void* sptr, const void* gptr) {
    unsigned int s = (unsigned int)__cvta_generic_to_shared(sptr);
    asm volatile("cp.async.cg.shared.global [%0], [%1], 16;\n" :: "r"(s), "l"(gptr));
}
__device__ __forceinline__ void cp_commit() { asm volatile("cp.async.commit_group;\n"); }
__device__ __forceinline__ void cp_wait0()  { asm volatile("cp.async.wait_group 0;\n"); }
__device__ __forceinline__ void cp_wait1()  { asm volatile("cp.async.wait_group 1;\n"); }

// block reduce (sum,sum) over 256 threads
__device__ __forceinline__ float2 block_reduce_sum2(float a, float b) {
    __shared__ float sa[8], sb[8];
    for (int o = 16; o; o >>= 1) {
        a += __shfl_xor_sync(0xffffffffu, a, o);
        b += __shfl_xor_sync(0xffffffffu, b, o);
    }
    int w = threadIdx.x >> 5, l = threadIdx.x & 31;
    if (l == 0) { sa[w] = a; sb[w] = b; }
    __syncthreads();
    if (w == 0) {
        a = (l < 8) ? sa[l] : 0.f;
        b = (l < 8) ? sb[l] : 0.f;
        for (int o = 4; o; o >>= 1) {
            a += __shfl_xor_sync(0xffffffffu, a, o);
            b += __shfl_xor_sync(0xffffffffu, b, o);
        }
        if (l == 0) { sa[0] = a; sb[0] = b; }
    }
    __syncthreads();
    return make_float2(sa[0], sb[0]);
}

// ---------------- fused fp32 -> fp16 weight conversion ----------------------
__global__ void wconv_kernel(const float* __restrict__ wa, const float* __restrict__ wp,
                             const float* __restrict__ wf, const float* __restrict__ wm,
                             __half* __restrict__ dst) {
    long i = ((long)blockIdx.x * blockDim.x + threadIdx.x) * 4;
    if (i >= W_TOTAL) return;
    const float* src;
    long off;
    if (i < WP_OFF)      { src = wa; off = i - WA_OFF; }
    else if (i < WF_OFF) { src = wp; off = i - WP_OFF; }
    else if (i < WM_OFF) { src = wf; off = i - WF_OFF; }
    else                 { src = wm; off = i - WM_OFF; }
    float4 v = *(const float4*)(src + off);
    *(__half2*)(dst + i)     = __floats2half2_rn(v.x, v.y);
    *(__half2*)(dst + i + 2) = __floats2half2_rn(v.z, v.w);
}

// ---------------- layernorm: fp32 in, fp16 out -------------------------------
__global__ void ln_kernel(const float* __restrict__ x,
                          const float* __restrict__ g,
                          const float* __restrict__ b,
                          __half* __restrict__ out) {
    long row = blockIdx.x;
    const float4* xr = (const float4*)(x + row * CC);
    int t = threadIdx.x;
    float4 v = xr[t];
    float s  = v.x + v.y + v.z + v.w;
    float ss = v.x * v.x + v.y * v.y + v.z * v.z + v.w * v.w;
    float2 r = block_reduce_sum2(s, ss);
    float mean = r.x * (1.0f / CC);
    float var  = r.y * (1.0f / CC) - mean * mean;
    float rstd = rsqrtf(var + 1e-5f);
    float4 gv = ((const float4*)g)[t];
    float4 bv = ((const float4*)b)[t];
    float ox = (v.x - mean) * rstd * gv.x + bv.x;
    float oy = (v.y - mean) * rstd * gv.y + bv.y;
    float oz = (v.z - mean) * rstd * gv.z + bv.z;
    float ow = (v.w - mean) * rstd * gv.w + bv.w;
    __half* op = out + row * CC + t * 4;
    *(__half2*)(op)     = __floats2half2_rn(ox, oy);
    *(__half2*)(op + 2) = __floats2half2_rn(oz, ow);
}

// ---------------- softmax over fp16 rows of length 2048 ----------------------
__global__ void softmax_kernel(__half* __restrict__ att) {
    long row = blockIdx.x;
    __half* p = att + row * (long)TT;
    int t = threadIdx.x;                 // 256 threads, 8 halfs each
    uint4 raw = ((uint4*)p)[t];
    __half2* hp = (__half2*)&raw;
    float f[8];
    #pragma unroll
    for (int j = 0; j < 4; j++) {
        float2 d = __half22float2(hp[j]);
        f[2 * j] = d.x; f[2 * j + 1] = d.y;
    }
    float m = -1e30f;
    #pragma unroll
    for (int j = 0; j < 8; j++) m = fmaxf(m, f[j]);
    __shared__ float sm[8];
    for (int o = 16; o; o >>= 1) m = fmaxf(m, __shfl_xor_sync(0xffffffffu, m, o));
    int w = t >> 5, l = t & 31;
    if (l == 0) sm[w] = m;
    __syncthreads();
    if (w == 0) {
        m = (l < 8) ? sm[l] : -1e30f;
        for (int o = 4; o; o >>= 1) m = fmaxf(m, __shfl_xor_sync(0xffffffffu, m, o));
        if (l == 0) sm[0] = m;
    }
    __syncthreads();
    m = sm[0];
    float s = 0.f;
    #pragma unroll
    for (int j = 0; j < 8; j++) { f[j] = expf(f[j] - m); s += f[j]; }
    float2 rr = block_reduce_sum2(s, 0.f);
    float inv = 1.0f / rr.x;
    #pragma unroll
    for (int j = 0; j < 4; j++)
        hp[j] = __floats2half2_rn(f[2 * j] * inv, f[2 * j + 1] * inv);
    ((uint4*)p)[t] = raw;
}

// ---------------- GEMM geometry (R6 schedule, frozen) ------------------------
#define EPI_SCALE 0
#define EPI_BIAS  1
#define EPI_GELU  2
#define EPI_RES   3

#define BM 128
#define BN 128
#define BK 32
#define A_LD 40                        // halfs; 80B rows
#define BNN_LD 136                     // halfs; 272B rows
#define A_TILE_H (BM * A_LD)           // 5120 halfs
#define STAGE_H  (2 * A_TILE_H)        // A + B (NT 5120, NN 4352 -> pad)
#define EPI_LD 68                      // fp32 epilogue staging, per warp 64x68
#define EPI_LDH 72                     // fp16 epilogue staging
#define GEMM_SMEM_BYTES (4 * 64 * EPI_LD * 4)   // 69632 (covers 2*STAGE_H*2 = 40960)
#define GEMM_H_SMEM_BYTES (4 * 64 * EPI_LDH * 2 > 2 * STAGE_H * 2 ? 4 * 64 * EPI_LDH * 2 : 2 * STAGE_H * 2)

// ---------------- fp32-accum GEMM (fc, mproj) --------------------------------
template<bool TRANS_B, int EPI, bool OUT_HALF>
__global__ void __launch_bounds__(128, 2)
gemm_kernel(const __half* __restrict__ A, const __half* __restrict__ B,
            const float* __restrict__ bias, const float* __restrict__ res,
            void* __restrict__ Cv,
            int M, int N, int K, int lda, int ldb, int ldc,
            long sA, long sB, long sC, float alpha) {
    extern __shared__ char smem[];

    long batch = blockIdx.z;
    A += batch * sA;
    B += batch * sB;

    const int tid  = threadIdx.x;
    const int warp = tid >> 5;
    const int lane = tid & 31;
    const int wm   = warp & 1;
    const int wn   = warp >> 1;
    const int bm   = blockIdx.y * BM;
    const int bn   = blockIdx.x * BN;

    const int ra = tid >> 2;
    const int ca = (tid & 3) * 8;
    const int rb = tid >> 4;
    const int cb = (tid & 15) * 8;

    wmma::fragment<wmma::accumulator, 16, 16, 16, float> fc[4][4];
    #pragma unroll
    for (int i = 0; i < 4; i++)
        #pragma unroll
        for (int j = 0; j < 4; j++)
            wmma::fill_fragment(fc[i][j], 0.0f);

    auto load_tile = [&](int k0, int s) {
        __half* As = (__half*)smem + s * STAGE_H;
        __half* Bs = As + A_TILE_H;
        #pragma unroll
        for (int i = 0; i < 4; i++)
            cp_async16(As + (ra + i * 32) * A_LD + ca,
                       A + (long)(bm + ra + i * 32) * lda + k0 + ca);
        if (TRANS_B) {
            #pragma unroll
            for (int i = 0; i < 4; i++)
                cp_async16(Bs + (ra + i * 32) * A_LD + ca,
                           B + (long)(bn + ra + i * 32) * ldb + k0 + ca);
        } else {
            #pragma unroll
            for (int i = 0; i < 4; i++)
                cp_async16(Bs + (rb + i * 8) * BNN_LD + cb,
                           B + (long)(k0 + rb + i * 8) * ldb + bn + cb);
        }
        cp_commit();
    };

    const int nk = K / BK;
    load_tile(0, 0);

    for (int it = 0; it < nk; it++) {
        const int cur = it & 1;
        if (it + 1 < nk) {
            load_tile((it + 1) * BK, cur ^ 1);
            cp_wait1();
        } else {
            cp_wait0();
        }
        __syncthreads();

        const __half* As = (const __half*)smem + cur * STAGE_H;
        const __half* Bs = As + A_TILE_H;

        #pragma unroll
        for (int kk = 0; kk < BK; kk += 16) {
            wmma::fragment<wmma::matrix_a, 16, 16, 16, __half, wmma::row_major> fa[4];
            #pragma unroll
            for (int i = 0; i < 4; i++)
                wmma::load_matrix_sync(fa[i], As + (wm * 64 + i * 16) * A_LD + kk, A_LD);
            if (TRANS_B) {
                wmma::fragment<wmma::matrix_b, 16, 16, 16, __half, wmma::col_major> fb[4];
                #pragma unroll
                for (int j = 0; j < 4; j++)
                    wmma::load_matrix_sync(fb[j], Bs + (wn * 64 + j * 16) * A_LD + kk, A_LD);
                #pragma unroll
                for (int i = 0; i < 4; i++)
                    #pragma unroll
                    for (int j = 0; j < 4; j++)
                        wmma::mma_sync(fc[i][j], fa[i], fb[j], fc[i][j]);
            } else {
                wmma::fragment<wmma::matrix_b, 16, 16, 16, __half, wmma::row_major> fb[4];
                #pragma unroll
                for (int j = 0; j < 4; j++)
                    wmma::load_matrix_sync(fb[j], Bs + kk * BNN_LD + wn * 64 + j * 16, BNN_LD);
                #pragma unroll
                for (int i = 0; i < 4; i++)
                    #pragma unroll
                    for (int j = 0; j < 4; j++)
                        wmma::mma_sync(fc[i][j], fa[i], fb[j], fc[i][j]);
            }
        }
        __syncthreads();
    }

    float* wbuf = (float*)smem + warp * 64 * EPI_LD;
    #pragma unroll
    for (int i = 0; i < 4; i++)
        #pragma unroll
        for (int j = 0; j < 4; j++)
            wmma::store_matrix_sync(wbuf + (i * 16) * EPI_LD + j * 16,
                                    fc[i][j], EPI_LD, wmma::mem_row_major);
    __syncwarp();

    const int grow = bm + wm * 64;
    const int gcol = bn + wn * 64;
    #pragma unroll
    for (int l = 0; l < 32; l++) {
        int idx = l * 32 + lane;
        int r = idx >> 4;
        int c = (idx & 15) * 4;
        float4 v = *(float4*)(wbuf + r * EPI_LD + c);
        v.x *= alpha; v.y *= alpha; v.z *= alpha; v.w *= alpha;
        if (EPI >= 1) {
            float4 bv = *(const float4*)(bias + gcol + c);
            v.x += bv.x; v.y += bv.y; v.z += bv.z; v.w += bv.w;
        }
        if (EPI == EPI_GELU) {
            v.x = gelu_f(v.x); v.y = gelu_f(v.y); v.z = gelu_f(v.z); v.w = gelu_f(v.w);
        }
        if (EPI == EPI_RES) {
            float4 rv = *(const float4*)(res + (long)(grow + r) * ldc + gcol + c);
            v.x += rv.x; v.y += rv.y; v.z += rv.z; v.w += rv.w;
        }
        if (OUT_HALF) {
            __half* Cp = (__half*)Cv + batch * sC + (long)(grow + r) * ldc + gcol + c;
            *(__half2*)(Cp)     = __floats2half2_rn(v.x, v.y);
            *(__half2*)(Cp + 2) = __floats2half2_rn(v.z, v.w);
        } else {
            float* Cp = (float*)Cv + batch * sC + (long)(grow + r) * ldc + gcol + c;
            *(float4*)Cp = v;
        }
    }
}

// ---------------- fp16-accum GEMM (qkv, qk, av, proj): 3 CTAs/SM -------------
template<bool TRANS_B, int EPI, bool OUT_HALF>
__global__ void __launch_bounds__(128, 3)
gemm_h(const __half* __restrict__ A, const __half* __restrict__ B,
       const float* __restrict__ bias, const float* __restrict__ res,
       void* __restrict__ Cv,
       int M, int N, int K, int lda, int ldb, int ldc,
       long sA, long sB, long sC, float alpha) {
    extern __shared__ char smem[];

    long batch = blockIdx.z;
    A += batch * sA;
    B += batch * sB;

    const int tid  = threadIdx.x;
    const int warp = tid >> 5;
    const int lane = tid & 31;
    const int wm   = warp & 1;
    const int wn   = warp >> 1;
    const int bm   = blockIdx.y * BM;
    const int bn   = blockIdx.x * BN;

    const int ra = tid >> 2;
    const int ca = (tid & 3) * 8;
    const int rb = tid >> 4;
    const int cb = (tid & 15) * 8;

    wmma::fragment<wmma::accumulator, 16, 16, 16, __half> fc[4][4];
    #pragma unroll
    for (int i = 0; i < 4; i++)
        #pragma unroll
        for (int j = 0; j < 4; j++)
            wmma::fill_fragment(fc[i][j], __float2half(0.0f));

    auto load_tile = [&](int k0, int s) {
        __half* As = (__half*)smem + s * STAGE_H;
        __half* Bs = As + A_TILE_H;
        #pragma unroll
        for (int i = 0; i < 4; i++)
            cp_async16(As + (ra + i * 32) * A_LD + ca,
                       A + (long)(bm + ra + i * 32) * lda + k0 + ca);
        if (TRANS_B) {
            #pragma unroll
            for (int i = 0; i < 4; i++)
                cp_async16(Bs + (ra + i * 32) * A_LD + ca,
                           B + (long)(bn + ra + i * 32) * ldb + k0 + ca);
        } else {
            #pragma unroll
            for (int i = 0; i < 4; i++)
                cp_async16(Bs + (rb + i * 8) * BNN_LD + cb,
                           B + (long)(k0 + rb + i * 8) * ldb + bn + cb);
        }
        cp_commit();
    };

    const int nk = K / BK;
    load_tile(0, 0);

    for (int it = 0; it < nk; it++) {
        const int cur = it & 1;
        if (it + 1 < nk) {
            load_tile((it + 1) * BK, cur ^ 1);
            cp_wait1();
        } else {
            cp_wait0();
        }
        __syncthreads();

        const __half* As = (const __half*)smem + cur * STAGE_H;
        const __half* Bs = As + A_TILE_H;

        #pragma unroll
        for (int kk = 0; kk < BK; kk += 16) {
            wmma::fragment<wmma::matrix_a, 16, 16, 16, __half, wmma::row_major> fa[4];
            #pragma unroll
            for (int i = 0; i < 4; i++)
                wmma::load_matrix_sync(fa[i], As + (wm * 64 + i * 16) * A_LD + kk, A_LD);
            if (TRANS_B) {
                wmma::fragment<wmma::matrix_b, 16, 16, 16, __half, wmma::col_major> fb[4];
                #pragma unroll
                for (int j = 0; j < 4; j++)
                    wmma::load_matrix_sync(fb[j], Bs + (wn * 64 + j * 16) * A_LD + kk, A_LD);
                #pragma unroll
                for (int i = 0; i < 4; i++)
                    #pragma unroll
                    for (int j = 0; j < 4; j++)
                        wmma::mma_sync(fc[i][j], fa[i], fb[j], fc[i][j]);
            } else {
                wmma::fragment<wmma::matrix_b, 16, 16, 16, __half, wmma::row_major> fb[4];
                #pragma unroll
                for (int j = 0; j < 4; j++)
                    wmma::load_matrix_sync(fb[j], Bs + kk * BNN_LD + wn * 64 + j * 16, BNN_LD);
                #pragma unroll
                for (int i = 0; i < 4; i++)
                    #pragma unroll
                    for (int j = 0; j < 4; j++)
                        wmma::mma_sync(fc[i][j], fa[i], fb[j], fc[i][j]);
            }
        }
        __syncthreads();
    }

    // --- epilogue: warp-private fp16 smem staging -----------------------------
    __half* wbuf = (__half*)smem + warp * 64 * EPI_LDH;
    #pragma unroll
    for (int i = 0; i < 4; i++)
        #pragma unroll
        for (int j = 0; j < 4; j++)
            wmma::store_matrix_sync(wbuf + (i * 16) * EPI_LDH + j * 16,
                                    fc[i][j], EPI_LDH, wmma::mem_row_major);
    __syncwarp();

    const int grow = bm + wm * 64;
    const int gcol = bn + wn * 64;
    #pragma unroll
    for (int l = 0; l < 32; l++) {
        int idx = l * 32 + lane;
        int r = idx >> 4;
        int c = (idx & 15) * 4;
        __half2 h0 = *(__half2*)(wbuf + r * EPI_LDH + c);
        __half2 h1 = *(__half2*)(wbuf + r * EPI_LDH + c + 2);
        float2 f0 = __half22float2(h0);
        float2 f1 = __half22float2(h1);
        float4 v = make_float4(f0.x * alpha, f0.y * alpha, f1.x * alpha, f1.y * alpha);
        if (EPI >= 1) {
            float4 bv = *(const float4*)(bias + gcol + c);
            v.x += bv.x; v.y += bv.y; v.z += bv.z; v.w += bv.w;
        }
        if (EPI == EPI_RES) {
            float4 rv = *(const float4*)(res + (long)(grow + r) * ldc + gcol + c);
            v.x += rv.x; v.y += rv.y; v.z += rv.z; v.w += rv.w;
        }
        if (OUT_HALF) {
            __half* Cp = (__half*)Cv + batch * sC + (long)(grow + r) * ldc + gcol + c;
            *(__half2*)(Cp)     = __floats2half2_rn(v.x, v.y);
            *(__half2*)(Cp + 2) = __floats2half2_rn(v.z, v.w);
        } else {
            float* Cp = (float*)Cv + batch * sC + (long)(grow + r) * ldc + gcol + c;
            *(float4*)Cp = v;
        }
    }
}

// ---------------- host side --------------------------------------------------
template<bool TB, int EPI, bool OH>
static void launch_gemm(const __half* A, const __half* B, const float* bias,
                        const float* res, void* C,
                        int M, int N, int K, int lda, int ldb, int ldc,
                        long sA, long sB, long sC, int batch, float alpha) {
    cudaFuncSetAttribute(gemm_kernel<TB, EPI, OH>,
                         cudaFuncAttributeMaxDynamicSharedMemorySize, GEMM_SMEM_BYTES);
    dim3 grid(N / BN, M / BM, batch);
    gemm_kernel<TB, EPI, OH><<<grid, 128, GEMM_SMEM_BYTES>>>(
        A, B, bias, res, C, M, N, K, lda, ldb, ldc, sA, sB, sC, alpha);
}

template<bool TB, int EPI, bool OH>
static void launch_gemm_h(const __half* A, const __half* B, const float* bias,
                          const float* res, void* C,
                          int M, int N, int K, int lda, int ldb, int ldc,
                          long sA, long sB, long sC, int batch, float alpha) {
    cudaFuncSetAttribute(gemm_h<TB, EPI, OH>,
                         cudaFuncAttributeMaxDynamicSharedMemorySize, GEMM_H_SMEM_BYTES);
    dim3 grid(N / BN, M / BM, batch);
    gemm_h<TB, EPI, OH><<<grid, 128, GEMM_H_SMEM_BYTES>>>(
        A, B, bias, res, C, M, N, K, lda, ldb, ldc, sA, sB, sC, alpha);
}

extern "C" void kernel_launch(void* const* d_in, const int* in_sizes, int n_in,
                              void* d_out, int out_size) {
    const float* x       = (const float*)d_in[0];
    const float* ln1_g   = (const float*)d_in[1];
    const float* ln1_b   = (const float*)d_in[2];
    const float* w_attn  = (const float*)d_in[3];
    const float* b_attn  = (const float*)d_in[4];
    const float* w_proj  = (const float*)d_in[5];
    const float* b_proj  = (const float*)d_in[6];
    const float* ln2_g   = (const float*)d_in[7];
    const float* ln2_b   = (const float*)d_in[8];
    const float* w_fc    = (const float*)d_in[9];
    const float* b_fc    = (const float*)d_in[10];
    const float* w_mproj = (const float*)d_in[11];
    const float* b_mproj = (const float*)d_in[12];
    float* xo = (float*)d_out;

    __half *h, *qkv, *att, *y, *h2, *fcb, *w16;
    cudaGetSymbolAddress((void**)&h,   s_h);
    cudaGetSymbolAddress((void**)&qkv, s_qkv);
    cudaGetSymbolAddress((void**)&att, s_att);
    cudaGetSymbolAddress((void**)&y,   s_y);
    cudaGetSymbolAddress((void**)&h2,  s_h2);
    cudaGetSymbolAddress((void**)&fcb, s_fc);
    cudaGetSymbolAddress((void**)&w16, s_w16);
    __half* wa = w16 + WA_OFF;
    __half* wp = w16 + WP_OFF;
    __half* wf = w16 + WF_OFF;
    __half* wm = w16 + WM_OFF;

    const long sQK  = (long)TT * 3 * CC;
    const long sAtt = (long)TT * TT;
    const long sY   = (long)TT * CC;

    // 0) all weights fp32 -> fp16, one launch
    wconv_kernel<<<(unsigned)((W_TOTAL / 4 + 255) / 256), 256>>>(w_attn, w_proj, w_fc, w_mproj, w16);

    // 1) h = LN1(x)
    ln_kernel<<<MROWS, 256>>>(x, ln1_g, ln1_b, h);
    // 2) qkv = h @ w_attn + b_attn        [8192,3072] fp16 accum, fp16 out
    launch_gemm_h<false, EPI_BIAS, true>(h, wa, b_attn, nullptr, qkv,
                                         MROWS, 3 * CC, CC, CC, 3 * CC, 3 * CC,
                                         0, 0, 0, 1, 1.0f);
    // 3) att = (q @ k^T) / 32             batched, fp16 accum
    launch_gemm_h<true, EPI_SCALE, true>(qkv, qkv + CC, nullptr, nullptr, att,
                                         TT, TT, CC, 3 * CC, 3 * CC, TT,
                                         sQK, sQK, sAtt, BB, 0.03125f);
    // 4) softmax rows (fp16 in/out, fp32 math)
    softmax_kernel<<<BB * TT, 256>>>(att);
    // 5) y = att @ v                      batched, fp16 accum
    launch_gemm_h<false, EPI_SCALE, true>(att, qkv + 2 * CC, nullptr, nullptr, y,
                                          TT, CC, TT, TT, 3 * CC, CC,
                                          sAtt, sQK, sY, BB, 1.0f);
    // 6) x1 = y @ w_proj + b_proj + x  -> d_out (fp32 out; fp16 accum is safe:
    //    attention branch magnitude ~0.01 vs output ~1)
    launch_gemm_h<false, EPI_RES, false>(y, wp, b_proj, x, xo,
                                         MROWS, CC, CC, CC, CC, CC,
                                         0, 0, 0, 1, 1.0f);
    // 7) h2 = LN2(x1)
    ln_kernel<<<MROWS, 256>>>(xo, ln2_g, ln2_b, h2);
    // 8) fc = gelu(h2 @ w_fc + b_fc)      fp32 accum (mlp branch is large)
    launch_gemm<false, EPI_GELU, true>(h2, wf, b_fc, nullptr, fcb,
                                       MROWS, HH, CC, CC, HH, HH,
                                       0, 0, 0, 1, 1.0f);
    // 9) out = fc @ w_mlp_proj + b + x1   fp32 accum, in-place residual
    launch_gemm<false, EPI_RES, false>(fcb, wm, b_mproj, xo, xo,
                                       MROWS, CC, HH, HH, CC, CC,
                                       0, 0, 0, 1, 1.0f);
}

// round 17
// speedup vs baseline: 1.0177x; 1.0177x over previous
#include <cuda_runtime.h>
#include <cuda_fp16.h>
#include <mma.h>
#include <math.h>
#include <cstdint>

using namespace nvcuda;

// Problem dims (fixed by the reference)
#define BB 4
#define TT 2048
#define CC 1024
#define HH 4096
#define MROWS (BB * TT)          // 8192

// ---------------- scratch (device globals; no allocation allowed) ----------
__device__ __half s_h   [MROWS * CC];          // ln1 out (fp16)
__device__ __half s_qkv [MROWS * 3 * CC];      // qkv (fp16)
__device__ __half s_att [(long)BB * TT * TT];  // attention logits/probs (fp16)
__device__ __half s_y   [MROWS * CC];          // att @ v (fp16)
__device__ __half s_h2  [MROWS * CC];          // ln2 out (fp16)
__device__ __half s_fc  [MROWS * HH];          // gelu(fc) (fp16)
// fp16 weight copies (one contiguous region, converted by a single kernel)
#define WA_OFF 0L
#define WP_OFF ((long)CC * 3 * CC)
#define WF_OFF (WP_OFF + (long)CC * CC)
#define WM_OFF (WF_OFF + (long)CC * HH)
#define W_TOTAL (WM_OFF + (long)HH * CC)
__device__ __half s_w16[W_TOTAL];

// ---------------- helpers ---------------------------------------------------
__device__ __forceinline__ float gelu_f(float x) {
    const float c = 0.7978845608028654f;
    float x3 = x * x * x;
    return 0.5f * x * (1.0f + tanhf(c * (x + 0.044715f * x3)));
}

__device__ __forceinline__ void cp_async16(void* sptr, const void* gptr) {
    unsigned int s = (unsigned int)__cvta_generic_to_shared(sptr);
    asm volatile("cp.async.cg.shared.global [%0], [%1], 16;\n" :: "r"(s), "l"(gptr));
}
__device__ __forceinline__ void cp_commit() { asm volatile("cp.async.commit_group;\n"); }
__device__ __forceinline__ void cp_wait0()  { asm volatile("cp.async.wait_group 0;\n"); }
__device__ __forceinline__ void cp_wait1()  { asm volatile("cp.async.wait_group 1;\n"); }

// block reduce (sum,sum) over 256 threads
__device__ __forceinline__ float2 block_reduce_sum2(float a, float b) {
    __shared__ float sa[8], sb[8];
    for (int o = 16; o; o >>= 1) {
        a += __shfl_xor_sync(0xffffffffu, a, o);
        b += __shfl_xor_sync(0xffffffffu, b, o);
    }
    int w = threadIdx.x >> 5, l = threadIdx.x & 31;
    if (l == 0) { sa[w] = a; sb[w] = b; }
    __syncthreads();
    if (w == 0) {
        a = (l < 8) ? sa[l] : 0.f;
        b = (l < 8) ? sb[l] : 0.f;
        for (int o = 4; o; o >>= 1) {
            a += __shfl_xor_sync(0xffffffffu, a, o);
            b += __shfl_xor_sync(0xffffffffu, b, o);
        }
        if (l == 0) { sa[0] = a; sb[0] = b; }
    }
    __syncthreads();
    return make_float2(sa[0], sb[0]);
}

// block reduce (max,max) over 256 threads
__device__ __forceinline__ float2 block_reduce_max2(float a, float b) {
    __shared__ float sa[8], sb[8];
    for (int o = 16; o; o >>= 1) {
        a = fmaxf(a, __shfl_xor_sync(0xffffffffu, a, o));
        b = fmaxf(b, __shfl_xor_sync(0xffffffffu, b, o));
    }
    int w = threadIdx.x >> 5, l = threadIdx.x & 31;
    if (l == 0) { sa[w] = a; sb[w] = b; }
    __syncthreads();
    if (w == 0) {
        a = (l < 8) ? sa[l] : -1e30f;
        b = (l < 8) ? sb[l] : -1e30f;
        for (int o = 4; o; o >>= 1) {
            a = fmaxf(a, __shfl_xor_sync(0xffffffffu, a, o));
            b = fmaxf(b, __shfl_xor_sync(0xffffffffu, b, o));
        }
        if (l == 0) { sa[0] = a; sb[0] = b; }
    }
    __syncthreads();
    return make_float2(sa[0], sb[0]);
}

// ---------------- fused fp32 -> fp16 weight conversion ----------------------
__global__ void wconv_kernel(const float* __restrict__ wa, const float* __restrict__ wp,
                             const float* __restrict__ wf, const float* __restrict__ wm,
                             __half* __restrict__ dst) {
    long i = ((long)blockIdx.x * blockDim.x + threadIdx.x) * 4;
    if (i >= W_TOTAL) return;
    const float* src;
    long off;
    if (i < WP_OFF)      { src = wa; off = i - WA_OFF; }
    else if (i < WF_OFF) { src = wp; off = i - WP_OFF; }
    else if (i < WM_OFF) { src = wf; off = i - WF_OFF; }
    else                 { src = wm; off = i - WM_OFF; }
    float4 v = *(const float4*)(src + off);
    *(__half2*)(dst + i)     = __floats2half2_rn(v.x, v.y);
    *(__half2*)(dst + i + 2) = __floats2half2_rn(v.z, v.w);
}

// ---------------- layernorm: fp32 in, fp16 out -------------------------------
__global__ void ln_kernel(const float* __restrict__ x,
                          const float* __restrict__ g,
                          const float* __restrict__ b,
                          __half* __restrict__ out) {
    long row = blockIdx.x;
    const float4* xr = (const float4*)(x + row * CC);
    int t = threadIdx.x;
    float4 v = xr[t];
    float s  = v.x + v.y + v.z + v.w;
    float ss = v.x * v.x + v.y * v.y + v.z * v.z + v.w * v.w;
    float2 r = block_reduce_sum2(s, ss);
    float mean = r.x * (1.0f / CC);
    float var  = r.y * (1.0f / CC) - mean * mean;
    float rstd = rsqrtf(var + 1e-5f);
    float4 gv = ((const float4*)g)[t];
    float4 bv = ((const float4*)b)[t];
    float ox = (v.x - mean) * rstd * gv.x + bv.x;
    float oy = (v.y - mean) * rstd * gv.y + bv.y;
    float oz = (v.z - mean) * rstd * gv.z + bv.z;
    float ow = (v.w - mean) * rstd * gv.w + bv.w;
    __half* op = out + row * CC + t * 4;
    *(__half2*)(op)     = __floats2half2_rn(ox, oy);
    *(__half2*)(op + 2) = __floats2half2_rn(oz, ow);
}

// ------ softmax over fp16 rows of length 2048; TWO rows per block ------------
__global__ void softmax_kernel(__half* __restrict__ att) {
    long row = (long)blockIdx.x * 2;
    __half* p0 = att + row * (long)TT;
    __half* p1 = p0 + TT;
    int t = threadIdx.x;                 // 256 threads, 8 halfs per row each
    uint4 raw0 = ((uint4*)p0)[t];
    uint4 raw1 = ((uint4*)p1)[t];
    __half2* h0 = (__half2*)&raw0;
    __half2* h1 = (__half2*)&raw1;
    float f[8], g[8];
    #pragma unroll
    for (int j = 0; j < 4; j++) {
        float2 d0 = __half22float2(h0[j]);
        float2 d1 = __half22float2(h1[j]);
        f[2 * j] = d0.x; f[2 * j + 1] = d0.y;
        g[2 * j] = d1.x; g[2 * j + 1] = d1.y;
    }
    float m0 = -1e30f, m1 = -1e30f;
    #pragma unroll
    for (int j = 0; j < 8; j++) { m0 = fmaxf(m0, f[j]); m1 = fmaxf(m1, g[j]); }
    float2 mm = block_reduce_max2(m0, m1);
    float s0 = 0.f, s1 = 0.f;
    #pragma unroll
    for (int j = 0; j < 8; j++) {
        f[j] = expf(f[j] - mm.x); s0 += f[j];
        g[j] = expf(g[j] - mm.y); s1 += g[j];
    }
    float2 ss = block_reduce_sum2(s0, s1);
    float inv0 = 1.0f / ss.x, inv1 = 1.0f / ss.y;
    #pragma unroll
    for (int j = 0; j < 4; j++) {
        h0[j] = __floats2half2_rn(f[2 * j] * inv0, f[2 * j + 1] * inv0);
        h1[j] = __floats2half2_rn(g[2 * j] * inv1, g[2 * j + 1] * inv1);
    }
    ((uint4*)p0)[t] = raw0;
    ((uint4*)p1)[t] = raw1;
}

// ---------------- fp16 wmma GEMM: R6 schedule (frozen) -----------------------
// 4 warps, 64x64 warp tiles, BK=32, 2-stage cp.async, loads issued first
#define EPI_SCALE 0
#define EPI_BIAS  1
#define EPI_GELU  2
#define EPI_RES   3

#define BM 128
#define BN 128
#define BK 32
#define A_LD 40                        // halfs; 80B rows
#define BNN_LD 136                     // halfs; 272B rows
#define A_TILE_H (BM * A_LD)           // 5120 halfs
#define STAGE_H  (2 * A_TILE_H)        // A + B (NT 5120, NN 4352 -> pad)
#define EPI_LD 68                      // fp32 epilogue staging, per warp 64x68
#define GEMM_SMEM_BYTES (4 * 64 * EPI_LD * 4)   // 69632 (covers 2*STAGE_H*2 = 40960)

template<bool TRANS_B, int EPI, bool OUT_HALF>
__global__ void __launch_bounds__(128, 2)
gemm_kernel(const __half* __restrict__ A, const __half* __restrict__ B,
            const float* __restrict__ bias, const float* __restrict__ res,
            void* __restrict__ Cv,
            int M, int N, int K, int lda, int ldb, int ldc,
            long sA, long sB, long sC, float alpha) {
    extern __shared__ char smem[];

    long batch = blockIdx.z;
    A += batch * sA;
    B += batch * sB;

    const int tid  = threadIdx.x;
    const int warp = tid >> 5;
    const int lane = tid & 31;
    const int wm   = warp & 1;   // 0..1 -> 64-row slab
    const int wn   = warp >> 1;  // 0..1 -> 64-col slab
    const int bm   = blockIdx.y * BM;
    const int bn   = blockIdx.x * BN;

    // load coords (8-half = 16B chunks), 128 threads
    const int ra = tid >> 2;            // 0..31 rows (4 blocks of 32)
    const int ca = (tid & 3) * 8;       // 0..24
    const int rb = tid >> 4;            // 0..7 rows (4 blocks of 8) for B-NN
    const int cb = (tid & 15) * 8;      // 0..120

    wmma::fragment<wmma::accumulator, 16, 16, 16, float> fc[4][4];
    #pragma unroll
    for (int i = 0; i < 4; i++)
        #pragma unroll
        for (int j = 0; j < 4; j++)
            wmma::fill_fragment(fc[i][j], 0.0f);

    auto load_tile = [&](int k0, int s) {
        __half* As = (__half*)smem + s * STAGE_H;
        __half* Bs = As + A_TILE_H;
        #pragma unroll
        for (int i = 0; i < 4; i++)
            cp_async16(As + (ra + i * 32) * A_LD + ca,
                       A + (long)(bm + ra + i * 32) * lda + k0 + ca);
        if (TRANS_B) {
            #pragma unroll
            for (int i = 0; i < 4; i++)
                cp_async16(Bs + (ra + i * 32) * A_LD + ca,
                           B + (long)(bn + ra + i * 32) * ldb + k0 + ca);
        } else {
            #pragma unroll
            for (int i = 0; i < 4; i++)
                cp_async16(Bs + (rb + i * 8) * BNN_LD + cb,
                           B + (long)(k0 + rb + i * 8) * ldb + bn + cb);
        }
        cp_commit();
    };

    const int nk = K / BK;
    load_tile(0, 0);

    for (int it = 0; it < nk; it++) {
        const int cur = it & 1;
        if (it + 1 < nk) {
            load_tile((it + 1) * BK, cur ^ 1);
            cp_wait1();
        } else {
            cp_wait0();
        }
        __syncthreads();

        const __half* As = (const __half*)smem + cur * STAGE_H;
        const __half* Bs = As + A_TILE_H;

        #pragma unroll
        for (int kk = 0; kk < BK; kk += 16) {
            wmma::fragment<wmma::matrix_a, 16, 16, 16, __half, wmma::row_major> fa[4];
            #pragma unroll
            for (int i = 0; i < 4; i++)
                wmma::load_matrix_sync(fa[i], As + (wm * 64 + i * 16) * A_LD + kk, A_LD);
            if (TRANS_B) {
                wmma::fragment<wmma::matrix_b, 16, 16, 16, __half, wmma::col_major> fb[4];
                #pragma unroll
                for (int j = 0; j < 4; j++)
                    wmma::load_matrix_sync(fb[j], Bs + (wn * 64 + j * 16) * A_LD + kk, A_LD);
                #pragma unroll
                for (int i = 0; i < 4; i++)
                    #pragma unroll
                    for (int j = 0; j < 4; j++)
                        wmma::mma_sync(fc[i][j], fa[i], fb[j], fc[i][j]);
            } else {
                wmma::fragment<wmma::matrix_b, 16, 16, 16, __half, wmma::row_major> fb[4];
                #pragma unroll
                for (int j = 0; j < 4; j++)
                    wmma::load_matrix_sync(fb[j], Bs + kk * BNN_LD + wn * 64 + j * 16, BNN_LD);
                #pragma unroll
                for (int i = 0; i < 4; i++)
                    #pragma unroll
                    for (int j = 0; j < 4; j++)
                        wmma::mma_sync(fc[i][j], fa[i], fb[j], fc[i][j]);
            }
        }
        __syncthreads();
    }

    // --- epilogue: warp-private fp32 smem staging -----------------------------
    float* wbuf = (float*)smem + warp * 64 * EPI_LD;
    #pragma unroll
    for (int i = 0; i < 4; i++)
        #pragma unroll
        for (int j = 0; j < 4; j++)
            wmma::store_matrix_sync(wbuf + (i * 16) * EPI_LD + j * 16,
                                    fc[i][j], EPI_LD, wmma::mem_row_major);
    __syncwarp();

    const int grow = bm + wm * 64;
    const int gcol = bn + wn * 64;
    #pragma unroll
    for (int l = 0; l < 32; l++) {
        int idx = l * 32 + lane;          // 0..1023
        int r = idx >> 4;                 // 0..63
        int c = (idx & 15) * 4;           // 0..60
        float4 v = *(float4*)(wbuf + r * EPI_LD + c);
        v.x *= alpha; v.y *= alpha; v.z *= alpha; v.w *= alpha;
        if (EPI >= 1) {
            float4 bv = *(const float4*)(bias + gcol + c);
            v.x += bv.x; v.y += bv.y; v.z += bv.z; v.w += bv.w;
        }
        if (EPI == EPI_GELU) {
            v.x = gelu_f(v.x); v.y = gelu_f(v.y); v.z = gelu_f(v.z); v.w = gelu_f(v.w);
        }
        if (EPI == EPI_RES) {
            float4 rv = *(const float4*)(res + (long)(grow + r) * ldc + gcol + c);
            v.x += rv.x; v.y += rv.y; v.z += rv.z; v.w += rv.w;
        }
        if (OUT_HALF) {
            __half* Cp = (__half*)Cv + batch * sC + (long)(grow + r) * ldc + gcol + c;
            *(__half2*)(Cp)     = __floats2half2_rn(v.x, v.y);
            *(__half2*)(Cp + 2) = __floats2half2_rn(v.z, v.w);
        } else {
            float* Cp = (float*)Cv + batch * sC + (long)(grow + r) * ldc + gcol + c;
            *(float4*)Cp = v;
        }
    }
}

// ------ qk GEMM variant: fp16 accumulators, 3 CTAs/SM (NT, scale, half out) --
#define EPI_LDH 72   // half staging leading dim (multiple of 8)

__global__ void __launch_bounds__(128, 3)
gemm_qk_h(const __half* __restrict__ A, const __half* __restrict__ B,
          __half* __restrict__ C, int K, int lda, int ldb, int ldc,
          long sA, long sB, long sC, float alpha) {
    extern __shared__ char smem[];

    long batch = blockIdx.z;
    A += batch * sA;
    B += batch * sB;

    const int tid  = threadIdx.x;
    const int warp = tid >> 5;
    const int lane = tid & 31;
    const int wm   = warp & 1;
    const int wn   = warp >> 1;
    const int bm   = blockIdx.y * BM;
    const int bn   = blockIdx.x * BN;

    const int ra = tid >> 2;
    const int ca = (tid & 3) * 8;

    wmma::fragment<wmma::accumulator, 16, 16, 16, __half> fc[4][4];
    #pragma unroll
    for (int i = 0; i < 4; i++)
        #pragma unroll
        for (int j = 0; j < 4; j++)
            wmma::fill_fragment(fc[i][j], __float2half(0.0f));

    auto load_tile = [&](int k0, int s) {
        __half* As = (__half*)smem + s * STAGE_H;
        __half* Bs = As + A_TILE_H;
        #pragma unroll
        for (int i = 0; i < 4; i++)
            cp_async16(As + (ra + i * 32) * A_LD + ca,
                       A + (long)(bm + ra + i * 32) * lda + k0 + ca);
        #pragma unroll
        for (int i = 0; i < 4; i++)
            cp_async16(Bs + (ra + i * 32) * A_LD + ca,
                       B + (long)(bn + ra + i * 32) * ldb + k0 + ca);
        cp_commit();
    };

    const int nk = K / BK;
    load_tile(0, 0);

    for (int it = 0; it < nk; it++) {
        const int cur = it & 1;
        if (it + 1 < nk) {
            load_tile((it + 1) * BK, cur ^ 1);
            cp_wait1();
        } else {
            cp_wait0();
        }
        __syncthreads();

        const __half* As = (const __half*)smem + cur * STAGE_H;
        const __half* Bs = As + A_TILE_H;

        #pragma unroll
        for (int kk = 0; kk < BK; kk += 16) {
            wmma::fragment<wmma::matrix_a, 16, 16, 16, __half, wmma::row_major> fa[4];
            #pragma unroll
            for (int i = 0; i < 4; i++)
                wmma::load_matrix_sync(fa[i], As + (wm * 64 + i * 16) * A_LD + kk, A_LD);
            wmma::fragment<wmma::matrix_b, 16, 16, 16, __half, wmma::col_major> fb[4];
            #pragma unroll
            for (int j = 0; j < 4; j++)
                wmma::load_matrix_sync(fb[j], Bs + (wn * 64 + j * 16) * A_LD + kk, A_LD);
            #pragma unroll
            for (int i = 0; i < 4; i++)
                #pragma unroll
                for (int j = 0; j < 4; j++)
                    wmma::mma_sync(fc[i][j], fa[i], fb[j], fc[i][j]);
        }
        __syncthreads();
    }

    // --- epilogue: warp-private fp16 smem staging -----------------------------
    __half* wbuf = (__half*)smem + warp * 64 * EPI_LDH;
    #pragma unroll
    for (int i = 0; i < 4; i++)
        #pragma unroll
        for (int j = 0; j < 4; j++)
            wmma::store_matrix_sync(wbuf + (i * 16) * EPI_LDH + j * 16,
                                    fc[i][j], EPI_LDH, wmma::mem_row_major);
    __syncwarp();

    const int grow = bm + wm * 64;
    const int gcol = bn + wn * 64;
    #pragma unroll
    for (int l = 0; l < 32; l++) {
        int idx = l * 32 + lane;          // 0..1023
        int r = idx >> 4;                 // 0..63
        int c = (idx & 15) * 4;           // 0..60 (4 halfs per thread-chunk)
        __half2 h0 = *(__half2*)(wbuf + r * EPI_LDH + c);
        __half2 h1 = *(__half2*)(wbuf + r * EPI_LDH + c + 2);
        float2 f0 = __half22float2(h0);
        float2 f1 = __half22float2(h1);
        __half* Cp = C + batch * sC + (long)(grow + r) * ldc + gcol + c;
        *(__half2*)(Cp)     = __floats2half2_rn(f0.x * alpha, f0.y * alpha);
        *(__half2*)(Cp + 2) = __floats2half2_rn(f1.x * alpha, f1.y * alpha);
    }
}

// ---------------- host side --------------------------------------------------
template<bool TB, int EPI, bool OH>
static void launch_gemm(const __half* A, const __half* B, const float* bias,
                        const float* res, void* C,
                        int M, int N, int K, int lda, int ldb, int ldc,
                        long sA, long sB, long sC, int batch, float alpha) {
    cudaFuncSetAttribute(gemm_kernel<TB, EPI, OH>,
                         cudaFuncAttributeMaxDynamicSharedMemorySize, GEMM_SMEM_BYTES);
    dim3 grid(N / BN, M / BM, batch);
    gemm_kernel<TB, EPI, OH><<<grid, 128, GEMM_SMEM_BYTES>>>(
        A, B, bias, res, C, M, N, K, lda, ldb, ldc, sA, sB, sC, alpha);
}

extern "C" void kernel_launch(void* const* d_in, const int* in_sizes, int n_in,
                              void* d_out, int out_size) {
    const float* x       = (const float*)d_in[0];
    const float* ln1_g   = (const float*)d_in[1];
    const float* ln1_b   = (const float*)d_in[2];
    const float* w_attn  = (const float*)d_in[3];
    const float* b_attn  = (const float*)d_in[4];
    const float* w_proj  = (const float*)d_in[5];
    const float* b_proj  = (const float*)d_in[6];
    const float* ln2_g   = (const float*)d_in[7];
    const float* ln2_b   = (const float*)d_in[8];
    const float* w_fc    = (const float*)d_in[9];
    const float* b_fc    = (const float*)d_in[10];
    const float* w_mproj = (const float*)d_in[11];
    const float* b_mproj = (const float*)d_in[12];
    float* xo = (float*)d_out;

    __half *h, *qkv, *att, *y, *h2, *fcb, *w16;
    cudaGetSymbolAddress((void**)&h,   s_h);
    cudaGetSymbolAddress((void**)&qkv, s_qkv);
    cudaGetSymbolAddress((void**)&att, s_att);
    cudaGetSymbolAddress((void**)&y,   s_y);
    cudaGetSymbolAddress((void**)&h2,  s_h2);
    cudaGetSymbolAddress((void**)&fcb, s_fc);
    cudaGetSymbolAddress((void**)&w16, s_w16);
    __half* wa = w16 + WA_OFF;
    __half* wp = w16 + WP_OFF;
    __half* wf = w16 + WF_OFF;
    __half* wm = w16 + WM_OFF;

    const long sQK  = (long)TT * 3 * CC;
    const long sAtt = (long)TT * TT;
    const long sY   = (long)TT * CC;

    // 0) all weights fp32 -> fp16, one launch
    wconv_kernel<<<(unsigned)((W_TOTAL / 4 + 255) / 256), 256>>>(w_attn, w_proj, w_fc, w_mproj, w16);

    // 1) h = LN1(x)
    ln_kernel<<<MROWS, 256>>>(x, ln1_g, ln1_b, h);
    // 2) qkv = h @ w_attn + b_attn        [8192,3072] fp16 out
    launch_gemm<false, EPI_BIAS, true>(h, wa, b_attn, nullptr, qkv,
                                       MROWS, 3 * CC, CC, CC, 3 * CC, 3 * CC,
                                       0, 0, 0, 1, 1.0f);
    // 3) att = (q @ k^T) / 32             batched [2048,2048], fp16-accum GEMM
    {
        cudaFuncSetAttribute(gemm_qk_h,
                             cudaFuncAttributeMaxDynamicSharedMemorySize, GEMM_SMEM_BYTES);
        dim3 grid(TT / BN, TT / BM, BB);
        gemm_qk_h<<<grid, 128, GEMM_SMEM_BYTES>>>(
            qkv, qkv + CC, att, CC, 3 * CC, 3 * CC, TT, sQK, sQK, sAtt, 0.03125f);
    }
    // 4) softmax rows (fp16 in/out, fp32 math; 2 rows per block)
    softmax_kernel<<<BB * TT / 2, 256>>>(att);
    // 5) y = att @ v                      batched [2048,1024] fp16 out
    launch_gemm<false, EPI_SCALE, true>(att, qkv + 2 * CC, nullptr, nullptr, y,
                                        TT, CC, TT, TT, 3 * CC, CC,
                                        sAtt, sQK, sY, BB, 1.0f);
    // 6) x1 = y @ w_proj + b_proj + x  -> d_out (fp32)
    launch_gemm<false, EPI_RES, false>(y, wp, b_proj, x, xo,
                                       MROWS, CC, CC, CC, CC, CC,
                                       0, 0, 0, 1, 1.0f);
    // 7) h2 = LN2(x1)
    ln_kernel<<<MROWS, 256>>>(xo, ln2_g, ln2_b, h2);
    // 8) fc = gelu(h2 @ w_fc + b_fc)      [8192,4096] fp16 out
    launch_gemm<false, EPI_GELU, true>(h2, wf, b_fc, nullptr, fcb,
                                       MROWS, HH, CC, CC, HH, HH,
                                       0, 0, 0, 1, 1.0f);
    // 9) out = fc @ w_mlp_proj + b + x1   [8192,1024] fp32, in-place residual
    launch_gemm<false, EPI_RES, false>(fcb, wm, b_mproj, xo, xo,
                                       MROWS, CC, HH, HH, CC, CC,
                                       0, 0, 0, 1, 1.0f);
}